// round 1
// baseline (speedup 1.0000x reference)
#include <cuda_runtime.h>
#include <math.h>

#define NN 100000
#define NE 500000
#define DIMC 256
#define NH 8
#define DHC 32

// Scratch (device globals: no allocation allowed in kernel_launch)
__device__ float g_Q[NN * DIMC];
__device__ float g_K[NN * DIMC];
__device__ float g_V[NN * DIMC];
__device__ float g_wV[NN * DIMC];
__device__ float g_Z[NN * NH];
__device__ float g_cs[DIMC];
__device__ float g_cs2[DIMC];
__device__ int g_src[NE];
__device__ int g_dst[NE];

// ---------------------------------------------------------------------------
// Zero the accumulators that are atomically updated each launch.
// ---------------------------------------------------------------------------
__global__ void zero_kernel() {
    long total = (long)NN * DIMC + (long)NN * NH;
    long stride = (long)gridDim.x * blockDim.x;
    for (long i = (long)blockIdx.x * blockDim.x + threadIdx.x; i < total; i += stride) {
        if (i < (long)NN * DIMC) g_wV[i] = 0.0f;
        else                     g_Z[i - (long)NN * DIMC] = 0.0f;
    }
    if (blockIdx.x == 0 && threadIdx.x < DIMC) {
        g_cs[threadIdx.x]  = 0.0f;
        g_cs2[threadIdx.x] = 0.0f;
    }
}

// ---------------------------------------------------------------------------
// Convert edge_index to int32 src/dst. Handles both int64 (requested by the
// reference) and int32 (what JAX actually produces with x64 disabled).
// Detection: interpret as int64; if any of the first 64 entries has a nonzero
// high word, the data is really int32 pairs. Deterministic per launch.
// ---------------------------------------------------------------------------
__global__ void cvt_idx_kernel(const long long* __restrict__ e64) {
    const int* e32 = (const int*)e64;
    bool is64 = true;
    #pragma unroll
    for (int i = 0; i < 64; ++i) {
        if ((e64[i] >> 32) != 0) is64 = false;
    }
    long stride = (long)gridDim.x * blockDim.x;
    for (long e = (long)blockIdx.x * blockDim.x + threadIdx.x; e < NE; e += stride) {
        if (is64) {
            g_src[e] = (int)e64[e];
            g_dst[e] = (int)e64[NE + e];
        } else {
            g_src[e] = e32[e];
            g_dst[e] = e32[NE + e];
        }
    }
}

// ---------------------------------------------------------------------------
// QKV GEMM: C[100000, 768] = x[100000,256] @ [WQ | WK | WV]
// 128x128 tile, 256 threads, 8x8 per-thread microtile, BK=16.
// blockIdx.y in [0,6): selects weight matrix (y>>1) and 128-col half (y&1).
// ---------------------------------------------------------------------------
__global__ void qkv_gemm_kernel(const float* __restrict__ x,
                                const float* __restrict__ WQ,
                                const float* __restrict__ WK,
                                const float* __restrict__ WV) {
    __shared__ float As[128][17];
    __shared__ float Bs[16][128];

    int bn = blockIdx.y;
    const float* W = (bn < 2) ? WQ : (bn < 4) ? WK : WV;
    float* Cout    = (bn < 2) ? g_Q : (bn < 4) ? g_K : g_V;
    int colbase = (bn & 1) * 128;
    int row0 = blockIdx.x * 128;
    int tid = threadIdx.x;
    int tx = tid & 15;        // 16 col-groups of 8
    int ty = tid >> 4;        // 16 row-groups of 8

    float acc[8][8] = {};

    for (int k0 = 0; k0 < DIMC; k0 += 16) {
        // A tile: 128x16 = 512 float4, 2 per thread
        #pragma unroll
        for (int l = 0; l < 2; ++l) {
            int idx = tid + l * 256;
            int row = idx >> 2;
            int kk  = (idx & 3) << 2;
            float4 v = make_float4(0.f, 0.f, 0.f, 0.f);
            if (row0 + row < NN)
                v = *(const float4*)(x + (long)(row0 + row) * DIMC + k0 + kk);
            As[row][kk]     = v.x;
            As[row][kk + 1] = v.y;
            As[row][kk + 2] = v.z;
            As[row][kk + 3] = v.w;
        }
        // B tile: 16x128 = 512 float4, 2 per thread
        #pragma unroll
        for (int l = 0; l < 2; ++l) {
            int idx = tid + l * 256;
            int kr = idx >> 5;
            int c4 = (idx & 31) << 2;
            *(float4*)(&Bs[kr][c4]) =
                *(const float4*)(W + (long)(k0 + kr) * DIMC + colbase + c4);
        }
        __syncthreads();

        #pragma unroll
        for (int kk = 0; kk < 16; ++kk) {
            float a[8], b[8];
            #pragma unroll
            for (int i = 0; i < 8; ++i) a[i] = As[ty * 8 + i][kk];
            float4 b0 = *(float4*)(&Bs[kk][tx * 8]);
            float4 b1 = *(float4*)(&Bs[kk][tx * 8 + 4]);
            b[0] = b0.x; b[1] = b0.y; b[2] = b0.z; b[3] = b0.w;
            b[4] = b1.x; b[5] = b1.y; b[6] = b1.z; b[7] = b1.w;
            #pragma unroll
            for (int i = 0; i < 8; ++i)
                #pragma unroll
                for (int j = 0; j < 8; ++j)
                    acc[i][j] += a[i] * b[j];
        }
        __syncthreads();
    }

    #pragma unroll
    for (int i = 0; i < 8; ++i) {
        int row = row0 + ty * 8 + i;
        if (row < NN) {
            float4 o0 = make_float4(acc[i][0], acc[i][1], acc[i][2], acc[i][3]);
            float4 o1 = make_float4(acc[i][4], acc[i][5], acc[i][6], acc[i][7]);
            *(float4*)(Cout + (long)row * DIMC + colbase + tx * 8)     = o0;
            *(float4*)(Cout + (long)row * DIMC + colbase + tx * 8 + 4) = o1;
        }
    }
}

// ---------------------------------------------------------------------------
// Fused edge kernel: per 64-edge tile
//   Eh_tile = edge_attr_tile @ WE            (64x256, regs)
//   score[e,h] = exp(clip(scale * sum_dh Eh*K[src]*Q[dst], -5, 5))
//   atomicAdd wV[dst] += V[src]*score ;  Z[dst,h] += score
// 256 threads = 8 warps; warp ty owns edges [ty*8, ty*8+8), lane tx owns cols
// [tx*8, tx*8+8) (one head per lane since 8 cols within head boundary).
// ---------------------------------------------------------------------------
__global__ void edge_kernel(const float* __restrict__ ea,
                            const float* __restrict__ WE) {
    __shared__ float As[64][17];
    __shared__ float Bs[16][256];
    __shared__ float Ssc[64][NH];
    __shared__ int Ssrc[64], Sdst[64];

    int e0 = blockIdx.x * 64;
    int tid = threadIdx.x;
    int tx = tid & 31;
    int ty = tid >> 5;

    if (tid < 64) {
        int ge = e0 + tid;
        if (ge < NE) { Ssrc[tid] = g_src[ge]; Sdst[tid] = g_dst[ge]; }
        else         { Ssrc[tid] = 0;         Sdst[tid] = 0;         }
    }

    float acc[8][8] = {};

    for (int k0 = 0; k0 < DIMC; k0 += 16) {
        // A tile: 64x16 = 256 float4, 1 per thread
        {
            int row = tid >> 2;
            int kk  = (tid & 3) << 2;
            float4 v = make_float4(0.f, 0.f, 0.f, 0.f);
            if (e0 + row < NE)
                v = *(const float4*)(ea + (long)(e0 + row) * DIMC + k0 + kk);
            As[row][kk]     = v.x;
            As[row][kk + 1] = v.y;
            As[row][kk + 2] = v.z;
            As[row][kk + 3] = v.w;
        }
        // B tile: 16x256 = 1024 float4, 4 per thread
        #pragma unroll
        for (int l = 0; l < 4; ++l) {
            int idx = tid + l * 256;
            int kr = idx >> 6;
            int c4 = (idx & 63) << 2;
            *(float4*)(&Bs[kr][c4]) =
                *(const float4*)(WE + (long)(k0 + kr) * DIMC + c4);
        }
        __syncthreads();

        #pragma unroll
        for (int kk = 0; kk < 16; ++kk) {
            float a[8], b[8];
            #pragma unroll
            for (int i = 0; i < 8; ++i) a[i] = As[ty * 8 + i][kk];
            float4 b0 = *(float4*)(&Bs[kk][tx * 8]);
            float4 b1 = *(float4*)(&Bs[kk][tx * 8 + 4]);
            b[0] = b0.x; b[1] = b0.y; b[2] = b0.z; b[3] = b0.w;
            b[4] = b1.x; b[5] = b1.y; b[6] = b1.z; b[7] = b1.w;
            #pragma unroll
            for (int i = 0; i < 8; ++i)
                #pragma unroll
                for (int j = 0; j < 8; ++j)
                    acc[i][j] += a[i] * b[j];
        }
        __syncthreads();
    }

    // Epilogue: per-edge per-head score. All 32 lanes of a warp work the same
    // edge -> K/Q row gathers are fully coalesced (256 contiguous floats).
    const float scale = 0.17677669529663687f;  // 1/sqrt(32)
    #pragma unroll
    for (int i = 0; i < 8; ++i) {
        int el = ty * 8 + i;
        int ge = e0 + el;
        float partial = 0.0f;
        if (ge < NE) {
            const float* Kr = g_K + (long)Ssrc[el] * DIMC;
            const float* Qr = g_Q + (long)Sdst[el] * DIMC;
            float4 ka = *(const float4*)(Kr + tx * 8);
            float4 kb = *(const float4*)(Kr + tx * 8 + 4);
            float4 qa = *(const float4*)(Qr + tx * 8);
            float4 qb = *(const float4*)(Qr + tx * 8 + 4);
            partial  = acc[i][0] * ka.x * qa.x;
            partial += acc[i][1] * ka.y * qa.y;
            partial += acc[i][2] * ka.z * qa.z;
            partial += acc[i][3] * ka.w * qa.w;
            partial += acc[i][4] * kb.x * qb.x;
            partial += acc[i][5] * kb.y * qb.y;
            partial += acc[i][6] * kb.z * qb.z;
            partial += acc[i][7] * kb.w * qb.w;
        }
        // reduce across the 4 lanes that share a head (lanes 4h..4h+3)
        partial += __shfl_xor_sync(0xffffffffu, partial, 1);
        partial += __shfl_xor_sync(0xffffffffu, partial, 2);
        if ((tx & 3) == 0) {
            float s = partial * scale;
            s = fminf(5.0f, fmaxf(-5.0f, s));
            Ssc[el][tx >> 2] = expf(s);
        }
    }
    __syncthreads();

    // Scatter: thread = column; loop over edges; coalesced V load + atomicAdd.
    int c = tid;
    int hh = c >> 5;
    for (int el = 0; el < 64; ++el) {
        int ge = e0 + el;
        if (ge >= NE) break;
        float s = Ssc[el][hh];
        float val = g_V[(long)Ssrc[el] * DIMC + c] * s;
        atomicAdd(&g_wV[(long)Sdst[el] * DIMC + c], val);
    }
    // Z scatter: 64 edges x 8 heads = 512 adds over 256 threads
    for (int p = tid; p < 64 * NH; p += 256) {
        int el = p >> 3;
        int h  = p & 7;
        int ge = e0 + el;
        if (ge < NE) atomicAdd(&g_Z[(long)Sdst[el] * NH + h], Ssc[el][h]);
    }
}

// ---------------------------------------------------------------------------
// Residual + BN column statistics. Block handles 256 rows, thread = column.
// ---------------------------------------------------------------------------
__global__ void resid_stats_kernel(const float* __restrict__ x,
                                   float* __restrict__ out) {
    int c = threadIdx.x;
    int r0 = blockIdx.x * 256;
    int rend = min(NN, r0 + 256);
    float s = 0.0f, s2 = 0.0f;
    for (int n = r0; n < rend; ++n) {
        float z = g_Z[(long)n * NH + (c >> 5)] + 1e-6f;
        float h = x[(long)n * DIMC + c] + g_wV[(long)n * DIMC + c] / z;
        out[(long)n * DIMC + c] = h;
        s  += h;
        s2 += h * h;
    }
    atomicAdd(&g_cs[c],  s);
    atomicAdd(&g_cs2[c], s2);
}

// ---------------------------------------------------------------------------
// BatchNorm normalize (in-place on d_out).
// ---------------------------------------------------------------------------
__global__ void bn_norm_kernel(float* __restrict__ out,
                               const float* __restrict__ gamma,
                               const float* __restrict__ beta) {
    long total = (long)NN * DIMC;
    long stride = (long)gridDim.x * blockDim.x;
    const float invN = 1.0f / (float)NN;
    for (long i = (long)blockIdx.x * blockDim.x + threadIdx.x; i < total; i += stride) {
        int c = (int)(i & (DIMC - 1));
        float mean = g_cs[c] * invN;
        float var  = g_cs2[c] * invN - mean * mean;
        out[i] = (out[i] - mean) * rsqrtf(var + 1e-5f) * gamma[c] + beta[c];
    }
}

extern "C" void kernel_launch(void* const* d_in, const int* in_sizes, int n_in,
                              void* d_out, int out_size) {
    const float* x     = (const float*)d_in[0];
    const float* ea    = (const float*)d_in[1];
    const float* WQ    = (const float*)d_in[2];
    const float* WK    = (const float*)d_in[3];
    const float* WE    = (const float*)d_in[4];
    const float* WV    = (const float*)d_in[5];
    const float* gamma = (const float*)d_in[6];
    const float* beta  = (const float*)d_in[7];
    const long long* eidx = (const long long*)d_in[8];
    float* out = (float*)d_out;

    zero_kernel<<<1024, 256>>>();
    cvt_idx_kernel<<<512, 256>>>(eidx);

    dim3 gq((NN + 127) / 128, 6);
    qkv_gemm_kernel<<<gq, 256>>>(x, WQ, WK, WV);

    edge_kernel<<<(NE + 63) / 64, 256>>>(ea, WE);

    resid_stats_kernel<<<(NN + 255) / 256, 256>>>(x, out);
    bn_norm_kernel<<<2048, 256>>>(out, gamma, beta);
}

// round 3
// speedup vs baseline: 2.7990x; 2.7990x over previous
#include <cuda_runtime.h>
#include <cuda_bf16.h>
#include <math.h>
#include <stdint.h>

#define NN 100000
#define NE 500000
#define DIMC 256
#define NH 8

// ---------------------------------------------------------------------------
// Device-global scratch (no allocation allowed in kernel_launch)
// ---------------------------------------------------------------------------
__device__ float g_Q[NN * DIMC];
__device__ float g_K[NN * DIMC];
__device__ float g_V[NN * DIMC];
__device__ float g_wV[NN * DIMC];
__device__ float g_Z[NN * NH];
__device__ float g_S[NE * NH];
__device__ float g_cs[DIMC];
__device__ float g_cs2[DIMC];
__device__ int g_src[NE];
__device__ int g_dst[NE];
__device__ __nv_bfloat16 g_xh[NN * DIMC],  g_xl[NN * DIMC];
__device__ __nv_bfloat16 g_eah[NE * DIMC], g_eal[NE * DIMC];
__device__ __nv_bfloat16 g_Wh[768 * DIMC], g_Wl[768 * DIMC];     // [n][k], QKV concat
__device__ __nv_bfloat16 g_WEh[DIMC * DIMC], g_WEl[DIMC * DIMC]; // [n][k]

// ---------------------------------------------------------------------------
// Warp-MMA helpers (portable PTX: ldmatrix + mma.sync, sm_80+ features)
// ---------------------------------------------------------------------------
__device__ __forceinline__ uint32_t smem_u32(const void* p) {
    uint32_t a;
    asm("{ .reg .u64 t; cvta.to.shared.u64 t, %1; cvt.u32.u64 %0, t; }"
        : "=r"(a) : "l"(p));
    return a;
}

__device__ __forceinline__ void ldsm_x4(uint32_t* r, uint32_t addr) {
    asm volatile("ldmatrix.sync.aligned.m8n8.x4.shared.b16 {%0,%1,%2,%3}, [%4];"
                 : "=r"(r[0]), "=r"(r[1]), "=r"(r[2]), "=r"(r[3]) : "r"(addr));
}
__device__ __forceinline__ void ldsm_x2(uint32_t* r, uint32_t addr) {
    asm volatile("ldmatrix.sync.aligned.m8n8.x2.shared.b16 {%0,%1}, [%2];"
                 : "=r"(r[0]), "=r"(r[1]) : "r"(addr));
}
__device__ __forceinline__ void mma_bf16(float* d, const uint32_t* a, const uint32_t* b) {
    asm volatile(
        "mma.sync.aligned.m16n8k16.row.col.f32.bf16.bf16.f32 "
        "{%0,%1,%2,%3}, {%4,%5,%6,%7}, {%8,%9}, {%0,%1,%2,%3};"
        : "+f"(d[0]), "+f"(d[1]), "+f"(d[2]), "+f"(d[3])
        : "r"(a[0]), "r"(a[1]), "r"(a[2]), "r"(a[3]), "r"(b[0]), "r"(b[1]));
}

// ---------------------------------------------------------------------------
// Zero atomically-updated accumulators.
// ---------------------------------------------------------------------------
__global__ void zero_kernel() {
    long total = (long)NN * DIMC + (long)NN * NH;
    long stride = (long)gridDim.x * blockDim.x;
    for (long i = (long)blockIdx.x * blockDim.x + threadIdx.x; i < total; i += stride) {
        if (i < (long)NN * DIMC) g_wV[i] = 0.0f;
        else                     g_Z[i - (long)NN * DIMC] = 0.0f;
    }
    if (blockIdx.x == 0 && threadIdx.x < DIMC) {
        g_cs[threadIdx.x]  = 0.0f;
        g_cs2[threadIdx.x] = 0.0f;
    }
}

// ---------------------------------------------------------------------------
// edge_index -> int32 src/dst (handles int64 or int32 payload, deterministic)
// ---------------------------------------------------------------------------
__global__ void cvt_idx_kernel(const long long* __restrict__ e64) {
    const int* e32 = (const int*)e64;
    bool is64 = true;
    #pragma unroll
    for (int i = 0; i < 64; ++i)
        if ((e64[i] >> 32) != 0) is64 = false;
    long stride = (long)gridDim.x * blockDim.x;
    for (long e = (long)blockIdx.x * blockDim.x + threadIdx.x; e < NE; e += stride) {
        if (is64) { g_src[e] = (int)e64[e]; g_dst[e] = (int)e64[NE + e]; }
        else      { g_src[e] = e32[e];      g_dst[e] = e32[NE + e];      }
    }
}

// ---------------------------------------------------------------------------
// fp32 -> bf16 hi/lo split preps
// ---------------------------------------------------------------------------
__global__ void prep_x_kernel(const float* __restrict__ x) {
    long total = (long)NN * DIMC;
    long stride = (long)gridDim.x * blockDim.x;
    for (long i = (long)blockIdx.x * blockDim.x + threadIdx.x; i < total; i += stride) {
        float v = x[i];
        __nv_bfloat16 h = __float2bfloat16(v);
        g_xh[i] = h;
        g_xl[i] = __float2bfloat16(v - __bfloat162float(h));
    }
}

__global__ void prep_ea_kernel(const float* __restrict__ ea) {
    long total = (long)NE * DIMC;
    long stride = (long)gridDim.x * blockDim.x;
    for (long i = (long)blockIdx.x * blockDim.x + threadIdx.x; i < total; i += stride) {
        float v = ea[i];
        __nv_bfloat16 h = __float2bfloat16(v);
        g_eah[i] = h;
        g_eal[i] = __float2bfloat16(v - __bfloat162float(h));
    }
}

// Weights transposed into B-operand layout [n][k], split hi/lo.
__global__ void prep_w_kernel(const float* __restrict__ WQ, const float* __restrict__ WK,
                              const float* __restrict__ WV, const float* __restrict__ WE) {
    int i = blockIdx.x * 256 + threadIdx.x;   // 0 .. 1024*256-1
    if (i < 768 * DIMC) {
        int n = i >> 8;
        int k = i & 255;
        int m = n >> 8, nn = n & 255;
        const float* W = (m == 0) ? WQ : (m == 1) ? WK : WV;
        float v = W[k * DIMC + nn];
        __nv_bfloat16 h = __float2bfloat16(v);
        g_Wh[i] = h;
        g_Wl[i] = __float2bfloat16(v - __bfloat162float(h));
    } else {
        int j = i - 768 * DIMC;
        int n = j >> 8, k = j & 255;
        float v = WE[k * DIMC + n];
        __nv_bfloat16 h = __float2bfloat16(v);
        g_WEh[j] = h;
        g_WEl[j] = __float2bfloat16(v - __bfloat162float(h));
    }
}

// ---------------------------------------------------------------------------
// Warp-MMA split-bf16 GEMM, 128x128 block tile, K=256 in 8 chunks of 32.
// 8 warps in 4(M) x 2(N); each warp computes 32x64 via m16n8k16 bf16 mma.
// 3 MMAs per (mi,ni,k16): Ah*Bh + Ah*Bl + Al*Bh  (fp32 accumulate).
// EDGE=0: writes Q/K/V.  EDGE=1: fused per-edge head-score epilogue -> g_S.
// ---------------------------------------------------------------------------
template<int EDGE>
__global__ void __launch_bounds__(256, 2) mma_gemm_kernel() {
    // smem tiles padded to 40 bf16 per row (80B) -> conflict-free ldmatrix
    __shared__ __align__(16) __nv_bfloat16 sAh[128 * 40];
    __shared__ __align__(16) __nv_bfloat16 sAl[128 * 40];
    __shared__ __align__(16) __nv_bfloat16 sBh[128 * 40];
    __shared__ __align__(16) __nv_bfloat16 sBl[128 * 40];
    __shared__ int Ssrc[128], Sdst[128];

    const int tid  = threadIdx.x;
    const int wid  = tid >> 5;
    const int lane = tid & 31;
    const int wm   = wid & 3;    // 4 M-groups of 32 rows
    const int wn   = wid >> 2;   // 2 N-groups of 64 cols
    const int quad = lane & 3;
    const int qrow = lane >> 2;

    const int row0  = blockIdx.x * 128;
    const int nbase = blockIdx.y * 128;
    const int Mtot  = EDGE ? NE : NN;

    if (EDGE && tid < 128) {
        int ge = row0 + tid;
        if (ge > NE - 1) ge = NE - 1;
        Ssrc[tid] = g_src[ge];
        Sdst[tid] = g_dst[ge];
    }

    const uint4* Ah4 = EDGE ? (const uint4*)g_eah : (const uint4*)g_xh;
    const uint4* Al4 = EDGE ? (const uint4*)g_eal : (const uint4*)g_xl;
    const uint4* Bh4 = EDGE ? (const uint4*)g_WEh : (const uint4*)g_Wh;
    const uint4* Bl4 = EDGE ? (const uint4*)g_WEl : (const uint4*)g_Wl;

    float acc[2][8][4] = {};

    // ldmatrix base addresses (byte offsets within tiles, row stride 80B)
    const uint32_t bAh = smem_u32(sAh), bAl = smem_u32(sAl);
    const uint32_t bBh = smem_u32(sBh), bBl = smem_u32(sBl);
    const uint32_t aOff = (uint32_t)((wm * 32 + (lane & 15)) * 80 + (lane >> 4) * 16);
    const uint32_t bOffRow = (uint32_t)((wn * 64 + (lane & 7)) * 80 + ((lane >> 3) & 1) * 16);

    for (int kc = 0; kc < 8; ++kc) {
        __syncthreads();
        // Stage Ah/Al/Bh/Bl 128x32 chunks (each 512 uint4; 8 uint4 per thread)
        #pragma unroll
        for (int l = 0; l < 8; ++l) {
            int idx = tid + l * 256;
            int sel = idx >> 9;          // constant per l
            int w   = idx & 511;
            int row = w >> 2;
            int c4  = w & 3;
            const uint4* gsrc;
            __nv_bfloat16* sdst;
            long rowg;
            if (sel == 0)      { gsrc = Ah4; sdst = sAh; rowg = min(row0 + row, Mtot - 1); }
            else if (sel == 1) { gsrc = Al4; sdst = sAl; rowg = min(row0 + row, Mtot - 1); }
            else if (sel == 2) { gsrc = Bh4; sdst = sBh; rowg = nbase + row; }
            else               { gsrc = Bl4; sdst = sBl; rowg = nbase + row; }
            uint4 v = gsrc[rowg * 32 + kc * 4 + c4];
            *(uint4*)(sdst + row * 40 + c4 * 8) = v;
        }
        __syncthreads();

        #pragma unroll
        for (int s = 0; s < 2; ++s) {
            uint32_t ah[2][4], al[2][4];
            #pragma unroll
            for (int mi = 0; mi < 2; ++mi) {
                uint32_t o = aOff + (uint32_t)(mi * 16 * 80 + s * 32);
                ldsm_x4(ah[mi], bAh + o);
                ldsm_x4(al[mi], bAl + o);
            }
            #pragma unroll
            for (int ni = 0; ni < 8; ++ni) {
                uint32_t bo = bOffRow + (uint32_t)(ni * 8 * 80 + s * 32);
                uint32_t bh[2], bl[2];
                ldsm_x2(bh, bBh + bo);
                ldsm_x2(bl, bBl + bo);
                #pragma unroll
                for (int mi = 0; mi < 2; ++mi) {
                    mma_bf16(acc[mi][ni], ah[mi], bh);
                    mma_bf16(acc[mi][ni], ah[mi], bl);
                    mma_bf16(acc[mi][ni], al[mi], bh);
                }
            }
        }
    }

    if (EDGE) {
        // Per-edge head scores: this warp covers rows (edges) wm*32..+31 and
        // cols nbase + wn*64 .. +63 (= heads (nbase>>5)+wn*2 .. +1).
        const float scale = 0.17677669529663687f;  // 1/sqrt(32)
        #pragma unroll
        for (int mi = 0; mi < 2; ++mi) {
            #pragma unroll
            for (int rh = 0; rh < 2; ++rh) {
                int r  = wm * 32 + mi * 16 + qrow + rh * 8;
                int ge = row0 + r;
                const float* Kr = g_K + (long)Ssrc[r] * DIMC + nbase + wn * 64;
                const float* Qr = g_Q + (long)Sdst[r] * DIMC + nbase + wn * 64;
                #pragma unroll
                for (int h = 0; h < 2; ++h) {
                    float p = 0.0f;
                    #pragma unroll
                    for (int j = 0; j < 4; ++j) {
                        int ni = h * 4 + j;
                        int c  = ni * 8 + quad * 2;
                        float2 kv = *(const float2*)(Kr + c);
                        float2 qv = *(const float2*)(Qr + c);
                        p += acc[mi][ni][rh * 2 + 0] * kv.x * qv.x;
                        p += acc[mi][ni][rh * 2 + 1] * kv.y * qv.y;
                    }
                    p += __shfl_xor_sync(0xffffffffu, p, 1);
                    p += __shfl_xor_sync(0xffffffffu, p, 2);
                    if (quad == 0 && ge < NE) {
                        float sv = fminf(5.0f, fmaxf(-5.0f, p * scale));
                        g_S[(long)ge * NH + (nbase >> 5) + wn * 2 + h] = expf(sv);
                    }
                }
            }
        }
    } else {
        int by = blockIdx.y;
        float* Cout = (by < 2) ? g_Q : (by < 4) ? g_K : g_V;
        int colb = (by & 1) * 128;
        #pragma unroll
        for (int mi = 0; mi < 2; ++mi) {
            #pragma unroll
            for (int ni = 0; ni < 8; ++ni) {
                int r = row0 + wm * 32 + mi * 16 + qrow;
                int c = colb + wn * 64 + ni * 8 + quad * 2;
                if (r < NN)
                    *(float2*)(Cout + (long)r * DIMC + c) =
                        make_float2(acc[mi][ni][0], acc[mi][ni][1]);
                if (r + 8 < NN)
                    *(float2*)(Cout + (long)(r + 8) * DIMC + c) =
                        make_float2(acc[mi][ni][2], acc[mi][ni][3]);
            }
        }
    }
}

// ---------------------------------------------------------------------------
// Scatter: wV[dst] += V[src]*score ; Z[dst,h] += score.  32 edges per block.
// ---------------------------------------------------------------------------
__global__ void scatter_kernel() {
    __shared__ int ssrc[32], sdst[32];
    __shared__ float ssc[32][NH];
    int e0 = blockIdx.x * 32;
    int tid = threadIdx.x;
    if (tid < 32) {
        int ge = e0 + tid;
        ssrc[tid] = (ge < NE) ? g_src[ge] : 0;
        sdst[tid] = (ge < NE) ? g_dst[ge] : 0;
    }
    {
        int el = tid >> 3, h = tid & 7;
        int ge = e0 + el;
        ssc[el][h] = (ge < NE) ? g_S[(long)ge * NH + h] : 0.0f;
    }
    __syncthreads();
    int c = tid;
    int h = c >> 5;
    for (int el = 0; el < 32; ++el) {
        int ge = e0 + el;
        if (ge >= NE) break;
        float s = ssc[el][h];
        atomicAdd(&g_wV[(long)sdst[el] * DIMC + c], g_V[(long)ssrc[el] * DIMC + c] * s);
    }
    {
        int el = tid >> 3, h2 = tid & 7;
        int ge = e0 + el;
        if (ge < NE) atomicAdd(&g_Z[(long)sdst[el] * NH + h2], ssc[el][h2]);
    }
}

// ---------------------------------------------------------------------------
// Residual + BN column stats, then normalize.
// ---------------------------------------------------------------------------
__global__ void resid_stats_kernel(const float* __restrict__ x, float* __restrict__ out) {
    int c = threadIdx.x;
    int r0 = blockIdx.x * 256;
    int rend = min(NN, r0 + 256);
    float s = 0.0f, s2 = 0.0f;
    for (int n = r0; n < rend; ++n) {
        float z = g_Z[(long)n * NH + (c >> 5)] + 1e-6f;
        float h = x[(long)n * DIMC + c] + g_wV[(long)n * DIMC + c] / z;
        out[(long)n * DIMC + c] = h;
        s += h;
        s2 += h * h;
    }
    atomicAdd(&g_cs[c], s);
    atomicAdd(&g_cs2[c], s2);
}

__global__ void bn_norm_kernel(float* __restrict__ out,
                               const float* __restrict__ gamma,
                               const float* __restrict__ beta) {
    long total = (long)NN * DIMC;
    long stride = (long)gridDim.x * blockDim.x;
    const float invN = 1.0f / (float)NN;
    for (long i = (long)blockIdx.x * blockDim.x + threadIdx.x; i < total; i += stride) {
        int c = (int)(i & (DIMC - 1));
        float mean = g_cs[c] * invN;
        float var = g_cs2[c] * invN - mean * mean;
        out[i] = (out[i] - mean) * rsqrtf(var + 1e-5f) * gamma[c] + beta[c];
    }
}

extern "C" void kernel_launch(void* const* d_in, const int* in_sizes, int n_in,
                              void* d_out, int out_size) {
    const float* x     = (const float*)d_in[0];
    const float* ea    = (const float*)d_in[1];
    const float* WQ    = (const float*)d_in[2];
    const float* WK    = (const float*)d_in[3];
    const float* WE    = (const float*)d_in[4];
    const float* WV    = (const float*)d_in[5];
    const float* gamma = (const float*)d_in[6];
    const float* beta  = (const float*)d_in[7];
    const long long* eidx = (const long long*)d_in[8];
    float* out = (float*)d_out;

    zero_kernel<<<1024, 256>>>();
    cvt_idx_kernel<<<512, 256>>>(eidx);
    prep_x_kernel<<<2048, 256>>>(x);
    prep_ea_kernel<<<8192, 256>>>(ea);
    prep_w_kernel<<<1024, 256>>>(WQ, WK, WV, WE);

    // QKV: C[100000,768] -> 782 x 6 tiles of 128x128
    mma_gemm_kernel<0><<<dim3(782, 6), 256>>>();
    // Edge: Eh + fused score epilogue -> 3907 x 2 tiles
    mma_gemm_kernel<1><<<dim3(3907, 2), 256>>>();

    scatter_kernel<<<(NE + 31) / 32, 256>>>();
    resid_stats_kernel<<<(NN + 255) / 256, 256>>>(x, out);
    bn_norm_kernel<<<2048, 256>>>(out, gamma, beta);
}